// round 1
// baseline (speedup 1.0000x reference)
#include <cuda_runtime.h>

// Problem constants (KernelRepeatLinear_12481174962958)
#define Bv 8
#define Ev 2048
#define Sv 512
#define Kv 8
#define HALO (Kv - 1)          // 7 causal taps before current row
#define TE 32                  // E-rows per block
#define ROWS (TE + HALO)       // 39 scan rows per block (incl. halo)
#define THREADS 256

// out[b,e,j] = bias[j] + sum_k weight[k,j] * P[b, e-7+k, j]
// P[b,e',j]  = sum_{i<=j} x[b,e',i] * dv^(j-i)   (decayed inclusive prefix scan)
__global__ __launch_bounds__(THREADS, 2)
void krl_fused_kernel(const float* __restrict__ x,
                      const float* __restrict__ weight,
                      const float* __restrict__ bias,
                      const float* __restrict__ decay,
                      float* __restrict__ out)
{
    extern __shared__ float smem[];
    float* shP = smem;                    // ROWS * Sv   (scan results)
    float* shW = smem + ROWS * Sv;        // Kv * Sv
    float* shB = shW + Kv * Sv;           // Sv

    const int tid  = threadIdx.x;
    const int lane = tid & 31;
    const int warp = tid >> 5;

    const int blocksPerBatch = Ev / TE;
    const int b  = blockIdx.x / blocksPerBatch;
    const int t  = blockIdx.x % blocksPerBatch;
    const int e0 = t * TE;

    float dv = decay[1];
    dv = fminf(1.0f, fmaxf(0.9f, dv));

    // weights + bias into shared
    for (int i = tid; i < Kv * Sv; i += THREADS) shW[i] = weight[i];
    for (int i = tid; i < Sv; i += THREADS)      shB[i] = bias[i];

    // dv^16 via 4 squarings (exact 1.0 when dv == 1)
    const float dv2 = dv * dv, dv4 = dv2 * dv2, dv8 = dv4 * dv4, dv16 = dv8 * dv8;

    // ---------------- Phase 1: decayed prefix scans (one warp per row) ----------------
    for (int r = warp; r < ROWS; r += THREADS / 32) {
        const int g = e0 - HALO + r;            // global E-row
        float4* dst = (float4*)(shP + r * Sv);
        if (g < 0 || g >= Ev) {
            #pragma unroll
            for (int q = 0; q < 4; ++q) dst[4 * lane + q] = make_float4(0.f, 0.f, 0.f, 0.f);
            continue;
        }
        const float4* src = (const float4*)(x + ((size_t)b * Ev + g) * Sv);
        float4 a[4];
        #pragma unroll
        for (int q = 0; q < 4; ++q) a[q] = src[4 * lane + q];

        // segment total (zero incoming carry)
        float p = 0.f;
        #pragma unroll
        for (int q = 0; q < 4; ++q) {
            p = fmaf(dv, p, a[q].x);
            p = fmaf(dv, p, a[q].y);
            p = fmaf(dv, p, a[q].z);
            p = fmaf(dv, p, a[q].w);
        }
        // Kogge-Stone inclusive warp scan, combine factor dv^(16*d)
        float s = p;
        float f = dv16;
        #pragma unroll
        for (int d = 1; d < 32; d <<= 1) {
            float o = __shfl_up_sync(0xffffffffu, s, d);
            if (lane >= d) s = fmaf(f, o, s);
            f = f * f;
        }
        float carry = __shfl_up_sync(0xffffffffu, s, 1);
        if (lane == 0) carry = 0.f;

        // final pass: re-scan raw values seeded with carry, store to smem
        p = carry;
        #pragma unroll
        for (int q = 0; q < 4; ++q) {
            p = fmaf(dv, p, a[q].x); a[q].x = p;
            p = fmaf(dv, p, a[q].y); a[q].y = p;
            p = fmaf(dv, p, a[q].z); a[q].z = p;
            p = fmaf(dv, p, a[q].w); a[q].w = p;
            dst[4 * lane + q] = a[q];
        }
    }
    __syncthreads();

    // ---------------- Phase 2: 8-tap FIR over E with register sliding window ----------
    const int jq   = tid & 127;        // float4 column index (512/4 = 128)
    const int half = tid >> 7;         // split tile rows between two thread groups
    const int le0  = half * (TE / 2);

    float4 wreg[Kv];
    #pragma unroll
    for (int k = 0; k < Kv; ++k)
        wreg[k] = *(const float4*)(shW + k * Sv + 4 * jq);
    const float4 bias4 = *(const float4*)(shB + 4 * jq);

    // shared row r holds global E-row (e0-7+r); output local row le taps rows le..le+7
    float4 win[8];
    #pragma unroll
    for (int i = 0; i < 7; ++i)
        win[i] = *(const float4*)(shP + (le0 + i) * Sv + 4 * jq);

    float4* outp = (float4*)(out + ((size_t)b * Ev + e0) * Sv);

    #pragma unroll
    for (int s = 0; s < TE / 2; ++s) {
        const int le = le0 + s;
        win[(s + 7) & 7] = *(const float4*)(shP + (le + 7) * Sv + 4 * jq);
        float4 acc = bias4;
        #pragma unroll
        for (int k = 0; k < Kv; ++k) {
            const float4 v = win[(s + k) & 7];
            const float4 w = wreg[k];
            acc.x = fmaf(w.x, v.x, acc.x);
            acc.y = fmaf(w.y, v.y, acc.y);
            acc.z = fmaf(w.z, v.z, acc.z);
            acc.w = fmaf(w.w, v.w, acc.w);
        }
        outp[le * (Sv / 4) + jq] = acc;
    }
}

extern "C" void kernel_launch(void* const* d_in, const int* in_sizes, int n_in,
                              void* d_out, int out_size)
{
    const float* x      = (const float*)d_in[0];  // (B, E, S)
    const float* weight = (const float*)d_in[1];  // (K, S)
    const float* bias   = (const float*)d_in[2];  // (S,)
    const float* decay  = (const float*)d_in[3];  // (2, 1)
    float* out          = (float*)d_out;          // (B, E, S)

    const int smem_bytes = (ROWS * Sv + Kv * Sv + Sv) * (int)sizeof(float); // 96 KB
    cudaFuncSetAttribute(krl_fused_kernel,
                         cudaFuncAttributeMaxDynamicSharedMemorySize, smem_bytes);

    dim3 grid(Bv * (Ev / TE));   // 512 blocks
    dim3 block(THREADS);
    krl_fused_kernel<<<grid, block, smem_bytes>>>(x, weight, bias, decay, out);
}

// round 2
// speedup vs baseline: 1.0847x; 1.0847x over previous
#include <cuda_runtime.h>

// KernelRepeatLinear: out[b,e,j] = bias[j] + sum_k weight[k,j] * P[b, e-7+k, j]
// P[b,e,j] = sum_{i<=j} x[b,e,i] * dv^(j-i)   (decayed inclusive prefix scan over dim)
#define Bv 8
#define Ev 2048
#define Sv 512
#define Kv 8
#define EC 16          // E-rows per FIR thread
#define CPB 2          // chunks per FIR block (256 thr = 128 jq x 2 chunks)

// 33.5 MB global scratch for the scanned rows P (static __device__ array: allowed)
__device__ float g_P[(size_t)Bv * Ev * Sv];

// packed fp32x2 FMA (Blackwell): d = a*b + c elementwise on two packed floats
#define FMA_F32X2(d, a, b, c) \
    asm("fma.rn.f32x2 %0, %1, %2, %3;" : "=l"(d) : "l"(a), "l"(b), "l"(c))

// ---------------- Kernel 1: decayed prefix scan, one warp per row ----------------
__global__ __launch_bounds__(256)
void krl_scan_kernel(const float* __restrict__ x,
                     const float* __restrict__ decay)
{
    const int lane = threadIdx.x & 31;
    const int warp = threadIdx.x >> 5;
    const int row  = blockIdx.x * 8 + warp;       // flattened (b*Ev + e)

    float dv = decay[1];
    dv = fminf(1.0f, fmaxf(0.9f, dv));

    // dv^(i+1) for i in [0,16): dvp[15] == dv^16 (warp-scan hop factor)
    float dvp[16];
    dvp[0] = dv;
    #pragma unroll
    for (int i = 1; i < 16; ++i) dvp[i] = dvp[i - 1] * dv;

    const float4* src = (const float4*)(x + (size_t)row * Sv);
    float4 a[4];
    #pragma unroll
    for (int q = 0; q < 4; ++q) a[q] = src[4 * lane + q];

    // in-place serial scan of this lane's 16 elements (zero incoming carry)
    float p = 0.f;
    #pragma unroll
    for (int q = 0; q < 4; ++q) {
        p = fmaf(dv, p, a[q].x); a[q].x = p;
        p = fmaf(dv, p, a[q].y); a[q].y = p;
        p = fmaf(dv, p, a[q].z); a[q].z = p;
        p = fmaf(dv, p, a[q].w); a[q].w = p;
    }

    // Kogge-Stone inclusive warp scan of segment-ends, hop factor dv^(16*d)
    float s = p;
    float f = dvp[15];
    #pragma unroll
    for (int d = 1; d < 32; d <<= 1) {
        float o = __shfl_up_sync(0xffffffffu, s, d);
        if (lane >= d) s = fmaf(f, o, s);
        f = f * f;
    }
    float carry = __shfl_up_sync(0xffffffffu, s, 1);
    if (lane == 0) carry = 0.f;

    // apply carry with INDEPENDENT fmas: P_i = local_i + carry * dv^(i+1)
    #pragma unroll
    for (int q = 0; q < 4; ++q) {
        a[q].x = fmaf(carry, dvp[4 * q + 0], a[q].x);
        a[q].y = fmaf(carry, dvp[4 * q + 1], a[q].y);
        a[q].z = fmaf(carry, dvp[4 * q + 2], a[q].z);
        a[q].w = fmaf(carry, dvp[4 * q + 3], a[q].w);
    }

    float4* dst = (float4*)(g_P + (size_t)row * Sv);
    #pragma unroll
    for (int q = 0; q < 4; ++q) dst[4 * lane + q] = a[q];
}

// ---------------- Kernel 2: 8-tap causal FIR over E (packed f32x2 FMA) ----------
__global__ __launch_bounds__(256)
void krl_fir_kernel(const float* __restrict__ weight,
                    const float* __restrict__ bias,
                    float* __restrict__ out)
{
    const int jq    = threadIdx.x & 127;          // float4 column (512/4)
    const int cslot = threadIdx.x >> 7;           // 0 or 1
    const int blocksPerBatch = (Ev / EC) / CPB;   // 64
    const int b     = blockIdx.x / blocksPerBatch;
    const int chunk = (blockIdx.x % blocksPerBatch) * CPB + cslot;
    const int e0    = chunk * EC;

    // weights + bias as packed u64 pairs (one float4 = 2 x f32x2)
    ulonglong2 wv[Kv];
    #pragma unroll
    for (int k = 0; k < Kv; ++k)
        wv[k] = ((const ulonglong2*)(weight + k * Sv))[jq];
    const ulonglong2 bv = ((const ulonglong2*)bias)[jq];

    const ulonglong2* Pb = (const ulonglong2*)(g_P + (size_t)b * Ev * Sv);
    // row r occupies 128 ulonglong2; slot of row r in ring: (r - e0 + 7) & 7

    ulonglong2 win[8];
    #pragma unroll
    for (int i = 0; i < 7; ++i) {
        const int g = e0 - 7 + i;
        if (g >= 0) win[i] = Pb[(size_t)g * 128 + jq];
        else        { win[i].x = 0ull; win[i].y = 0ull; }
    }

    ulonglong2* outp = (ulonglong2*)(out + ((size_t)b * Ev + e0) * Sv);

    #pragma unroll
    for (int s = 0; s < EC; ++s) {
        win[(s + 7) & 7] = Pb[(size_t)(e0 + s) * 128 + jq];   // newest tap row
        ulonglong2 acc = bv;
        #pragma unroll
        for (int k = 0; k < Kv; ++k) {
            const ulonglong2 v = win[(s + k) & 7];
            FMA_F32X2(acc.x, wv[k].x, v.x, acc.x);
            FMA_F32X2(acc.y, wv[k].y, v.y, acc.y);
        }
        outp[(size_t)s * 128 + jq] = acc;
    }
}

extern "C" void kernel_launch(void* const* d_in, const int* in_sizes, int n_in,
                              void* d_out, int out_size)
{
    const float* x      = (const float*)d_in[0];  // (B, E, S)
    const float* weight = (const float*)d_in[1];  // (K, S)
    const float* bias   = (const float*)d_in[2];  // (S,)
    const float* decay  = (const float*)d_in[3];  // (2, 1)
    float* out          = (float*)d_out;          // (B, E, S)

    krl_scan_kernel<<<Bv * Ev / 8, 256>>>(x, decay);
    krl_fir_kernel<<<Bv * (Ev / EC) / CPB, 256>>>(weight, bias, out);
}

// round 3
// speedup vs baseline: 1.3099x; 1.2076x over previous
#include <cuda_runtime.h>

// KernelRepeatLinear: out[b,e,j] = bias[j] + sum_k weight[k,j] * P[b, e-7+k, j]
// P[b,e,j] = sum_{i<=j} x[b,e,i] * dv^(j-i)   (decayed inclusive prefix scan over dim)
#define Bv 8
#define Ev 2048
#define Sv 512
#define Kv 8
#define HALO (Kv - 1)
#define TE 16                 // output E-rows per block
#define ROWS (TE + HALO)      // 23 scanned rows (halo recomputed per block)
#define THREADS 256

// packed fp32x2 FMA (Blackwell): d = a*b + c on two packed floats
#define FMA_F32X2(d, a, b, c) \
    asm("fma.rn.f32x2 %0, %1, %2, %3;" : "=l"(d) : "l"(a), "l"(b), "l"(c))

__global__ __launch_bounds__(THREADS, 4)
void krl_fused2(const float* __restrict__ x,
                const float* __restrict__ weight,
                const float* __restrict__ bias,
                const float* __restrict__ decay,
                float* __restrict__ out)
{
    __shared__ float shP[ROWS * Sv];   // 47104 B (< 48 KB static limit)

    const int tid  = threadIdx.x;
    const int lane = tid & 31;
    const int warp = tid >> 5;

    const int blocksPerBatch = Ev / TE;           // 128
    const int b  = blockIdx.x / blocksPerBatch;
    const int t  = blockIdx.x % blocksPerBatch;
    const int e0 = t * TE;

    float dv = decay[1];
    dv = fminf(1.0f, fmaxf(0.9f, dv));

    // dv^(i+1), i in [0,16); dvp[15] == dv^16 (warp-scan hop factor)
    float dvp[16];
    dvp[0] = dv;
    #pragma unroll
    for (int i = 1; i < 16; ++i) dvp[i] = dvp[i - 1] * dv;

    // -------- Phase 1: decayed prefix scan of 23 rows (one warp per row) --------
    for (int r = warp; r < ROWS; r += THREADS / 32) {
        const int g = e0 - HALO + r;              // global E-row
        float4* dst = (float4*)(shP + r * Sv);
        if (g < 0) {                               // only first tile of a batch
            #pragma unroll
            for (int q = 0; q < 4; ++q) dst[4 * lane + q] = make_float4(0.f, 0.f, 0.f, 0.f);
            continue;
        }
        const float4* src = (const float4*)(x + ((size_t)b * Ev + g) * Sv);
        float4 a[4];
        #pragma unroll
        for (int q = 0; q < 4; ++q) a[q] = src[4 * lane + q];

        // in-place serial scan of this lane's 16 elems (zero incoming carry)
        float p = 0.f;
        #pragma unroll
        for (int q = 0; q < 4; ++q) {
            p = fmaf(dv, p, a[q].x); a[q].x = p;
            p = fmaf(dv, p, a[q].y); a[q].y = p;
            p = fmaf(dv, p, a[q].z); a[q].z = p;
            p = fmaf(dv, p, a[q].w); a[q].w = p;
        }
        // Kogge-Stone inclusive warp scan of segment ends, hop factor dv^(16*d)
        float s = p;
        float f = dvp[15];
        #pragma unroll
        for (int d = 1; d < 32; d <<= 1) {
            float o = __shfl_up_sync(0xffffffffu, s, d);
            if (lane >= d) s = fmaf(f, o, s);
            f = f * f;
        }
        float carry = __shfl_up_sync(0xffffffffu, s, 1);
        if (lane == 0) carry = 0.f;

        // apply carry with independent fmas: P_i = local_i + carry * dv^(i+1)
        #pragma unroll
        for (int q = 0; q < 4; ++q) {
            a[q].x = fmaf(carry, dvp[4 * q + 0], a[q].x);
            a[q].y = fmaf(carry, dvp[4 * q + 1], a[q].y);
            a[q].z = fmaf(carry, dvp[4 * q + 2], a[q].z);
            a[q].w = fmaf(carry, dvp[4 * q + 3], a[q].w);
            dst[4 * lane + q] = a[q];
        }
    }
    __syncthreads();

    // -------- Phase 2: 8-tap FIR over E; thread owns one float2 column ----------
    const int jq = tid;                            // float2 column, 0..255

    // weights/bias straight from global (L2-hot), packed as u64 for f32x2
    unsigned long long wv[Kv];
    #pragma unroll
    for (int k = 0; k < Kv; ++k)
        wv[k] = ((const unsigned long long*)(weight + k * Sv))[jq];
    const unsigned long long bv = ((const unsigned long long*)bias)[jq];

    // ring: slot (r & 7) holds smem row r (r = local scan row)
    unsigned long long win[8];
    #pragma unroll
    for (int i = 0; i < HALO; ++i)
        win[i] = ((const unsigned long long*)(shP + i * Sv))[jq];

    unsigned long long* outp =
        (unsigned long long*)(out + ((size_t)b * Ev + e0) * Sv);

    #pragma unroll
    for (int s = 0; s < TE; ++s) {
        win[(s + HALO) & 7] = ((const unsigned long long*)(shP + (s + HALO) * Sv))[jq];
        unsigned long long acc = bv;
        #pragma unroll
        for (int k = 0; k < Kv; ++k)
            FMA_F32X2(acc, wv[k], win[(s + k) & 7], acc);
        outp[(size_t)s * (Sv / 2) + jq] = acc;
    }
}

extern "C" void kernel_launch(void* const* d_in, const int* in_sizes, int n_in,
                              void* d_out, int out_size)
{
    const float* x      = (const float*)d_in[0];  // (B, E, S)
    const float* weight = (const float*)d_in[1];  // (K, S)
    const float* bias   = (const float*)d_in[2];  // (S,)
    const float* decay  = (const float*)d_in[3];  // (2, 1)
    float* out          = (float*)d_out;          // (B, E, S)

    krl_fused2<<<Bv * (Ev / TE), THREADS>>>(x, weight, bias, decay, out);
}